// round 14
// baseline (speedup 1.0000x reference)
#include <cuda_runtime.h>
#include <cuda_fp16.h>
#include <stdint.h>
#include <math.h>

typedef unsigned int u32;

#define TOKENS 4096
#define DIM    1024
#define QKV_N  3072
#define NH     16
#define HD     64
#define TSEQ   2048
#define BHEADS 32
// 0.125 * log2(e)
#define SCALE2 0.18033688011112042f

// ---------------- global scratch ----------------
__device__ float2 g_trig[TSEQ * 32];

// GEMM A operands: [M][K2] u32 (fp16 pairs along K), hi+lo split
__device__ u32 g_xh[TOKENS * DIM / 2],  g_xl[TOKENS * DIM / 2];
__device__ u32 g_oh2[TOKENS * DIM / 2], g_ol2[TOKENS * DIM / 2];
// GEMM B operands: [K2][N] u32 (fp16 pairs along K), rounded single
__device__ u32 g_wqh[DIM / 2 * QKV_N];
__device__ u32 g_wph[DIM / 2 * DIM];

// flash operands: Q split hi/lo, K/V rounded single (fp16 pairs)
__device__ u32 g_qh[BHEADS * TSEQ * 32], g_ql[BHEADS * TSEQ * 32];
__device__ u32 g_kh[BHEADS * TSEQ * 32];
__device__ u32 g_vth[BHEADS * HD * (TSEQ / 2)];

// ---------------- helpers ----------------
__device__ __forceinline__ void mma_f16(float c[4],
                                        const u32 a[4], const u32 b[2])
{
    asm volatile(
        "mma.sync.aligned.m16n8k16.row.col.f32.f16.f16.f32 "
        "{%0,%1,%2,%3}, {%4,%5,%6,%7}, {%8,%9}, {%0,%1,%2,%3};"
        : "+f"(c[0]), "+f"(c[1]), "+f"(c[2]), "+f"(c[3])
        : "r"(a[0]), "r"(a[1]), "r"(a[2]), "r"(a[3]),
          "r"(b[0]), "r"(b[1]));
}

__device__ __forceinline__ void ldsm_x4(u32 r[4], u32 saddr)
{
    asm volatile(
        "ldmatrix.sync.aligned.m8n8.x4.shared.b16 {%0,%1,%2,%3}, [%4];"
        : "=r"(r[0]), "=r"(r[1]), "=r"(r[2]), "=r"(r[3]) : "r"(saddr));
}

__device__ __forceinline__ void split_pack_f16(float x0, float x1,
                                               u32& hi, u32& lo)
{
    __half2 H = __floats2half2_rn(x0, x1);
    float2 hf = __half22float2(H);
    __half2 L = __floats2half2_rn(x0 - hf.x, x1 - hf.y);
    hi = *(u32*)&H;
    lo = *(u32*)&L;
}

__device__ __forceinline__ u32 pack_f16(float x0, float x1)
{
    __half2 H = __floats2half2_rn(x0, x1);
    return *(u32*)&H;
}

// FFMA-only exp2 (no MUFU)
__device__ __forceinline__ float exp2_fast(float x)
{
    x = fmaxf(x, -60.0f);
    float t  = __fadd_rn(x, 12582912.0f);
    int   n  = __float_as_int(t) << 23;
    float ni = __fadd_rn(t, -12582912.0f);
    float r  = __fadd_rn(x, -ni);
    float p  = 1.3333558e-3f;
    p = fmaf(p, r, 9.6181291e-3f);
    p = fmaf(p, r, 5.5504109e-2f);
    p = fmaf(p, r, 2.4022651e-1f);
    p = fmaf(p, r, 6.9314718e-1f);
    p = fmaf(p, r, 1.0f);
    return __int_as_float(__float_as_int(p) + n);
}

__device__ __forceinline__ void cp16(u32* smem_dst, const u32* gsrc)
{
    unsigned d = (unsigned)__cvta_generic_to_shared(smem_dst);
    asm volatile("cp.async.cg.shared.global [%0], [%1], 16;" :: "r"(d), "l"(gsrc));
}

// ---------------- prepass kernels ----------------
__global__ __launch_bounds__(256)
void split_pairs_rows(const float* __restrict__ src, u32* __restrict__ hi,
                      u32* __restrict__ lo, int npairs)
{
    int i = blockIdx.x * 256 + threadIdx.x;
    if (i >= npairs) return;
    float2 v = ((const float2*)src)[i];
    split_pack_f16(v.x, v.y, hi[i], lo[i]);
}

__global__ __launch_bounds__(256)
void pack_pairs_cols(const float* __restrict__ B, u32* __restrict__ hi,
                     int N, int K)
{
    int i = blockIdx.x * 256 + threadIdx.x;
    int K2 = K >> 1;
    if (i >= K2 * N) return;
    int k2 = i / N, n = i - k2 * N;
    hi[i] = pack_f16(B[(size_t)(2 * k2) * N + n],
                     B[(size_t)(2 * k2 + 1) * N + n]);
}

__global__ __launch_bounds__(256)
void trig_table()
{
    int idx = blockIdx.x * 256 + threadIdx.x;
    if (idx >= TSEQ * 32) return;
    int t = idx >> 5, i = idx & 31;
    float freq = expf(-9.210340371976184f * (float)i * (1.0f / 32.0f));
    float ang = (float)t * freq;
    float s, c;
    sincosf(ang, &s, &c);
    g_trig[idx] = make_float2(s, c);
}

// ---------------------------------------------------------------------------
// mma_gemm7: fp16 A-split 2-pass GEMM, 3-stage cp.async, ldmatrix A-frags.
// epi=0: C=A@B+bias. epi=1: fused rope+pack epilogue -> g_qh/g_ql/g_kh/g_vth.
// ---------------------------------------------------------------------------
#define A_ST  (128 * 20)
#define B_ST  (16 * 136)
#define STG_U32 (2 * A_ST + B_ST)
#define G7_SMEM (3 * STG_U32 * 4)    // 87552 B (>= 128*129*4 = 66048 staging)

__global__ __launch_bounds__(256, 2)
void mma_gemm7(const u32* __restrict__ Agh, const u32* __restrict__ Agl,
               const u32* __restrict__ Bgh,
               float* __restrict__ C, const float* __restrict__ bias,
               int N, int K, int epi)
{
    extern __shared__ u32 sm7[];

    const int tid  = threadIdx.x;
    const int wid  = tid >> 5;
    const int lane = tid & 31;
    const int r8   = lane >> 2;
    const int c4   = lane & 3;
    const int grp  = lane >> 3;
    const int wtn  = lane & 7;
    const int wm   = (wid >> 2) * 64;
    const int wn   = (wid & 3) * 32;
    const int brow = blockIdx.y, bcol = blockIdx.x;
    const int K2   = K >> 1;

    const u32 smbase = (u32)__cvta_generic_to_shared(sm7);
    const u32 lmA = (u32)(((grp & 1) * 8 + wtn) * 20 + (grp >> 1) * 4);

    const int ar  = tid & 127;
    const int acb = (tid >> 7) * 8;
    const u32* Aph = Agh + (size_t)(brow * 128 + ar) * K2 + acb;
    const u32* Apl = Agl + (size_t)(brow * 128 + ar) * K2 + acb;
    const int bk  = tid >> 4;
    const int bnc = (tid & 15) * 8;
    const u32* Bph = Bgh + (size_t)bk * N + bcol * 128 + bnc;

    float acc[4][4][4];
    #pragma unroll
    for (int i = 0; i < 4; i++)
        #pragma unroll
        for (int j = 0; j < 4; j++)
            #pragma unroll
            for (int r = 0; r < 4; r++) acc[i][j][r] = 0.f;

    auto issue = [&](int k2base, int s) {
        u32* st = sm7 + s * STG_U32;
        u32* aH = st + ar * 20 + acb;
        u32* aL = st + A_ST + ar * 20 + acb;
        cp16(aH,     Aph + k2base);
        cp16(aH + 4, Aph + k2base + 4);
        cp16(aL,     Apl + k2base);
        cp16(aL + 4, Apl + k2base + 4);
        u32* bH = st + 2 * A_ST + bk * 136 + bnc;
        cp16(bH,     Bph + (size_t)k2base * N);
        cp16(bH + 4, Bph + (size_t)k2base * N + 4);
        asm volatile("cp.async.commit_group;");
    };

    issue(0, 0);
    issue(16, 1);

    const int nst = K2 >> 4;
    int s = 0;
    for (int ks = 0; ks < nst; ks++) {
        asm volatile("cp.async.wait_group 1;");
        __syncthreads();
        if (ks + 2 < nst) {
            int s2 = s + 2; if (s2 >= 3) s2 -= 3;
            issue((ks + 2) * 16, s2);
        } else {
            asm volatile("cp.async.commit_group;");
        }

        const u32 stoff = (u32)(s * STG_U32);
        const u32 aHb = smbase + (stoff + lmA + wm * 20) * 4;
        const u32 aLb = aHb + A_ST * 4;
        const u32* bH = sm7 + stoff + 2 * A_ST;

        #pragma unroll
        for (int kk = 0; kk < 2; kk++) {
            const int kc = kk * 8 + c4;
            u32 bh[4][2];
            #pragma unroll
            for (int nf = 0; nf < 4; nf++) {
                const int n = wn + nf * 8 + r8;
                bh[nf][0] = bH[kc * 136 + n];
                bh[nf][1] = bH[(kc + 4) * 136 + n];
            }
            #pragma unroll
            for (int mf = 0; mf < 4; mf++) {
                u32 ah[4], al[4];
                const u32 moff = (u32)(mf * 16 * 20 + kk * 8) * 4;
                ldsm_x4(ah, aHb + moff);
                ldsm_x4(al, aLb + moff);
                #pragma unroll
                for (int nf = 0; nf < 4; nf++) {
                    mma_f16(acc[mf][nf], ah, bh[nf]);
                    mma_f16(acc[mf][nf], al, bh[nf]);
                }
            }
        }
        if (++s >= 3) s -= 3;
    }

    if (!epi) {
        #pragma unroll
        for (int nf = 0; nf < 4; nf++) {
            const int cg = bcol * 128 + wn + nf * 8 + c4 * 2;
            float bx = bias ? bias[cg]     : 0.f;
            float by = bias ? bias[cg + 1] : 0.f;
            #pragma unroll
            for (int mf = 0; mf < 4; mf++) {
                const int rg = brow * 128 + wm + mf * 16 + r8;
                float2 v0 = make_float2(acc[mf][nf][0] + bx, acc[mf][nf][1] + by);
                float2 v1 = make_float2(acc[mf][nf][2] + bx, acc[mf][nf][3] + by);
                *(float2*)(C + (size_t)rg * N + cg)       = v0;
                *(float2*)(C + (size_t)(rg + 8) * N + cg) = v1;
            }
        }
    } else {
        // ---- fused epilogue: stage tile in smem, rope/pack/scatter ----
        asm volatile("cp.async.wait_group 0;" ::: "memory");
        __syncthreads();
        float* S = (float*)sm7;   // [128][129]
        #pragma unroll
        for (int nf = 0; nf < 4; nf++) {
            const int cg = wn + nf * 8 + c4 * 2;
            #pragma unroll
            for (int mf = 0; mf < 4; mf++) {
                const int rg = wm + mf * 16 + r8;
                S[rg * 129 + cg]           = acc[mf][nf][0];
                S[rg * 129 + cg + 1]       = acc[mf][nf][1];
                S[(rg + 8) * 129 + cg]     = acc[mf][nf][2];
                S[(rg + 8) * 129 + cg + 1] = acc[mf][nf][3];
            }
        }
        __syncthreads();

        const int which = bcol >> 3;     // 0=q 1=k 2=v
        const int b     = brow >> 4;
        if (which < 2) {
            // rope + pack: warp handles 32 (row,head) units; lane = d-pair idx
            for (int uu = 0; uu < 32; uu++) {
                const int u    = wid * 32 + uu;
                const int head = u >> 7;
                const int row  = u & 127;
                const int tt   = (brow & 15) * 128 + row;
                const int h    = (bcol & 7) * 2 + head;
                const int bh   = b * 16 + h;
                const float* Sr = S + row * 129 + head * 64;
                const int i = lane;
                const int j = (i < 16) ? 2 * i : 2 * i - 32;
                float4 tc = *(const float4*)(&g_trig[tt * 32 + j]); // s0,c0,s1,c1
                float a0 = Sr[j],      a1 = Sr[j + 1];
                float b0 = Sr[j + 32], b1 = Sr[j + 33];
                float e0, e1;
                if (i < 16) {
                    e0 = a0 * tc.y - b0 * tc.x;
                    e1 = a1 * tc.w - b1 * tc.z;
                } else {
                    e0 = a0 * tc.x + b0 * tc.y;
                    e1 = a1 * tc.z + b1 * tc.w;
                }
                size_t po = ((size_t)bh * TSEQ + tt) * 32 + i;
                if (which == 0) {
                    u32 hi, lo;
                    split_pack_f16(e0 * SCALE2, e1 * SCALE2, hi, lo);
                    g_qh[po] = hi;
                    g_ql[po] = lo;
                } else {
                    g_kh[po] = pack_f16(e0, e1);
                }
            }
        } else {
            // v: transposed pack (pairs along t), coalesced along t2
            const int dq  = tid >> 6;       // 0..3
            const int t2l = tid & 63;
            const int t2g = (brow & 15) * 64 + t2l;
            #pragma unroll 4
            for (int dd = dq; dd < 128; dd += 4) {
                const int h  = (bcol & 7) * 2 + (dd >> 6);
                const int bh = b * 16 + h;
                u32 pv = pack_f16(S[(2 * t2l) * 129 + dd],
                                  S[(2 * t2l + 1) * 129 + dd]);
                g_vth[((size_t)bh * HD + (dd & 63)) * (TSEQ / 2) + t2g] = pv;
            }
        }
    }
}

// ---------------------------------------------------------------------------
// Flash attention: fp16 (Q split 2-pass S, P single-pass PV), ldmatrix,
// cp.async double-buffered, exp2 softmax. Epilogue writes split o directly.
// ---------------------------------------------------------------------------
#define FKS  36
#define FTILE (64 * FKS)

__global__ __launch_bounds__(256)
void flash_mma()
{
    __shared__ u32 Ksh[2 * FTILE];
    __shared__ u32 Vsh[2 * FTILE];

    const int bh   = blockIdx.y;
    const int qblk = gridDim.x - 1 - blockIdx.x;
    const int q0   = qblk * 128;

    const int tid  = threadIdx.x;
    const int w    = tid >> 5;
    const int lane = tid & 31;
    const int r8   = lane >> 2;
    const int c4   = lane & 3;
    const int grp  = lane >> 3;
    const int wtn  = lane & 7;

    const u32 Kbase = (u32)__cvta_generic_to_shared(Ksh);
    const u32 Vbase = (u32)__cvta_generic_to_shared(Vsh);
    const u32 lmF = (u32)(((grp >> 1) * 8 + wtn) * FKS + (grp & 1) * 4);

    u32 qh[4][4], ql[4][4];
    {
        const u32* Qh = g_qh + ((size_t)bh * TSEQ + q0 + w * 16) * 32;
        const u32* Ql = g_ql + ((size_t)bh * TSEQ + q0 + w * 16) * 32;
        #pragma unroll
        for (int g = 0; g < 4; g++) {
            qh[g][0] = Qh[(size_t)r8 * 32 + 8 * g + c4];
            qh[g][1] = Qh[(size_t)(r8 + 8) * 32 + 8 * g + c4];
            qh[g][2] = Qh[(size_t)r8 * 32 + 8 * g + c4 + 4];
            qh[g][3] = Qh[(size_t)(r8 + 8) * 32 + 8 * g + c4 + 4];
            ql[g][0] = Ql[(size_t)r8 * 32 + 8 * g + c4];
            ql[g][1] = Ql[(size_t)(r8 + 8) * 32 + 8 * g + c4];
            ql[g][2] = Ql[(size_t)r8 * 32 + 8 * g + c4 + 4];
            ql[g][3] = Ql[(size_t)(r8 + 8) * 32 + 8 * g + c4 + 4];
        }
    }

    float oacc[8][4];
    #pragma unroll
    for (int i = 0; i < 8; i++)
        #pragma unroll
        for (int j = 0; j < 4; j++) oacc[i][j] = 0.f;
    float m0 = -1e30f, m1 = -1e30f, l0 = 0.f, l1 = 0.f;

    const int row0 = q0 + w * 16 + r8;
    const int row1 = row0 + 8;

    const u32* Kgh = g_kh + (size_t)bh * TSEQ * 32;
    const u32* Vgh = g_vth + (size_t)bh * HD * (TSEQ / 2);

    const int lr = tid >> 2, lcb = (tid & 3) * 8;

    auto fissue = [&](int tile, int s) {
        const int k0 = tile * 64;
        const u32* kh = Kgh + (size_t)(k0 + lr) * 32 + lcb;
        const u32* vh = Vgh + (size_t)lr * (TSEQ / 2) + (k0 >> 1) + lcb;
        u32* dk = Ksh + s * FTILE + lr * FKS + lcb;
        u32* dv = Vsh + s * FTILE + lr * FKS + lcb;
        cp16(dk,     kh);
        cp16(dk + 4, kh + 4);
        cp16(dv,     vh);
        cp16(dv + 4, vh + 4);
        asm volatile("cp.async.commit_group;");
    };

    const int ntiles = 2 * qblk + 2;
    fissue(0, 0);

    for (int tile = 0; tile < ntiles; tile++) {
        asm volatile("cp.async.wait_group 0;");
        __syncthreads();
        if (tile + 1 < ntiles) fissue(tile + 1, (tile + 1) & 1);

        const u32 sboff = (u32)((tile & 1) * FTILE);
        const int k0 = tile * 64;

        const bool active = (k0 <= q0 + w * 16 + 15);
        if (active) {
            float sacc[8][4];
            #pragma unroll
            for (int i = 0; i < 8; i++)
                #pragma unroll
                for (int j = 0; j < 4; j++) sacc[i][j] = 0.f;

            const u32 kfb = Kbase + (sboff + lmF) * 4;
            #pragma unroll
            for (int g = 0; g < 4; g++) {
                #pragma unroll
                for (int nfp = 0; nfp < 4; nfp++) {
                    u32 kf[4];
                    ldsm_x4(kf, kfb + (u32)(nfp * 16 * FKS + 8 * g) * 4);
                    mma_f16(sacc[2 * nfp],     qh[g], kf);
                    mma_f16(sacc[2 * nfp],     ql[g], kf);
                    mma_f16(sacc[2 * nfp + 1], qh[g], kf + 2);
                    mma_f16(sacc[2 * nfp + 1], ql[g], kf + 2);
                }
            }

            if (k0 + 63 > row0) {
                #pragma unroll
                for (int nf = 0; nf < 8; nf++) {
                    const int n0 = k0 + nf * 8 + 2 * c4;
                    if (n0 > row0)     sacc[nf][0] = -1e30f;
                    if (n0 + 1 > row0) sacc[nf][1] = -1e30f;
                    if (n0 > row1)     sacc[nf][2] = -1e30f;
                    if (n0 + 1 > row1) sacc[nf][3] = -1e30f;
                }
            }

            float rm0 = -1e30f, rm1 = -1e30f;
            #pragma unroll
            for (int nf = 0; nf < 8; nf++) {
                rm0 = fmaxf(rm0, fmaxf(sacc[nf][0], sacc[nf][1]));
                rm1 = fmaxf(rm1, fmaxf(sacc[nf][2], sacc[nf][3]));
            }
            rm0 = fmaxf(rm0, __shfl_xor_sync(0xffffffffu, rm0, 1));
            rm0 = fmaxf(rm0, __shfl_xor_sync(0xffffffffu, rm0, 2));
            rm1 = fmaxf(rm1, __shfl_xor_sync(0xffffffffu, rm1, 1));
            rm1 = fmaxf(rm1, __shfl_xor_sync(0xffffffffu, rm1, 2));

            const float mn0 = fmaxf(m0, rm0);
            const float mn1 = fmaxf(m1, rm1);
            const float rs0 = exp2_fast(m0 - mn0);
            const float rs1 = exp2_fast(m1 - mn1);
            m0 = mn0; m1 = mn1;

            float sum0 = 0.f, sum1 = 0.f;
            #pragma unroll
            for (int nf = 0; nf < 8; nf++) {
                sacc[nf][0] = exp2_fast(sacc[nf][0] - mn0);
                sacc[nf][1] = exp2_fast(sacc[nf][1] - mn0);
                sacc[nf][2] = exp2_fast(sacc[nf][2] - mn1);
                sacc[nf][3] = exp2_fast(sacc[nf][3] - mn1);
                sum0 += sacc[nf][0] + sacc[nf][1];
                sum1 += sacc[nf][2] + sacc[nf][3];
            }
            sum0 += __shfl_xor_sync(0xffffffffu, sum0, 1);
            sum0 += __shfl_xor_sync(0xffffffffu, sum0, 2);
            sum1 += __shfl_xor_sync(0xffffffffu, sum1, 1);
            sum1 += __shfl_xor_sync(0xffffffffu, sum1, 2);
            l0 = l0 * rs0 + sum0;
            l1 = l1 * rs1 + sum1;

            #pragma unroll
            for (int nf = 0; nf < 8; nf++) {
                oacc[nf][0] *= rs0;
                oacc[nf][1] *= rs0;
                oacc[nf][2] *= rs1;
                oacc[nf][3] *= rs1;
            }

            const u32 vfb = Vbase + (sboff + lmF) * 4;
            #pragma unroll
            for (int g = 0; g < 4; g++) {
                u32 ph[4];
                ph[0] = pack_f16(sacc[2 * g][0],     sacc[2 * g][1]);
                ph[1] = pack_f16(sacc[2 * g][2],     sacc[2 * g][3]);
                ph[2] = pack_f16(sacc[2 * g + 1][0], sacc[2 * g + 1][1]);
                ph[3] = pack_f16(sacc[2 * g + 1][2], sacc[2 * g + 1][3]);
                #pragma unroll
                for (int nfp = 0; nfp < 4; nfp++) {
                    u32 vf[4];
                    ldsm_x4(vf, vfb + (u32)(nfp * 16 * FKS + 8 * g) * 4);
                    mma_f16(oacc[2 * nfp],     ph, vf);
                    mma_f16(oacc[2 * nfp + 1], ph, vf + 2);
                }
            }
        }
    }

    // epilogue: normalize and write split fp16 o directly (proj A-operand)
    const float inv0 = 1.0f / l0;
    const float inv1 = 1.0f / l1;
    const int b = bh >> 4, h = bh & 15;
    #pragma unroll
    for (int nf = 0; nf < 8; nf++) {
        const size_t i0 = ((size_t)(b * TSEQ) + row0) * 512 + h * 32 + nf * 4 + c4;
        const size_t i1 = ((size_t)(b * TSEQ) + row1) * 512 + h * 32 + nf * 4 + c4;
        split_pack_f16(oacc[nf][0] * inv0, oacc[nf][1] * inv0, g_oh2[i0], g_ol2[i0]);
        split_pack_f16(oacc[nf][2] * inv1, oacc[nf][3] * inv1, g_oh2[i1], g_ol2[i1]);
    }
}

// ---------------------------------------------------------------------------
extern "C" void kernel_launch(void* const* d_in, const int* in_sizes, int n_in,
                              void* d_out, int out_size)
{
    const float* x      = (const float*)d_in[0];
    const float* w_qkv  = (const float*)d_in[1];
    const float* w_proj = (const float*)d_in[2];
    const float* b_proj = (const float*)d_in[3];
    float* out = (float*)d_out;

    u32 *xh, *xl, *oh, *ol, *wqh, *wph;
    cudaGetSymbolAddress((void**)&xh,  g_xh);
    cudaGetSymbolAddress((void**)&xl,  g_xl);
    cudaGetSymbolAddress((void**)&oh,  g_oh2);
    cudaGetSymbolAddress((void**)&ol,  g_ol2);
    cudaGetSymbolAddress((void**)&wqh, g_wqh);
    cudaGetSymbolAddress((void**)&wph, g_wph);

    cudaFuncSetAttribute(mma_gemm7,
                         cudaFuncAttributeMaxDynamicSharedMemorySize, G7_SMEM);

    // 0) trig table + operand prepasses
    trig_table<<<(TSEQ * 32 + 255) / 256, 256>>>();
    const int xpairs = TOKENS * DIM / 2;
    split_pairs_rows<<<(xpairs + 255) / 256, 256>>>(x, xh, xl, xpairs);
    pack_pairs_cols<<<((DIM / 2) * QKV_N + 255) / 256, 256>>>(w_qkv, wqh, QKV_N, DIM);
    pack_pairs_cols<<<((DIM / 2) * DIM + 255) / 256, 256>>>(w_proj, wph, DIM, DIM);

    // 1) qkv = x @ w_qkv -> fused rope/pack -> g_qh/g_ql/g_kh/g_vth
    mma_gemm7<<<dim3(QKV_N / 128, TOKENS / 128), 256, G7_SMEM>>>(
        xh, xl, wqh, nullptr, nullptr, QKV_N, DIM, 1);

    // 2) flash attention (writes split o directly)
    flash_mma<<<dim3(TSEQ / 128, BHEADS), 256>>>();

    // 3) out = o @ w_proj + b_proj
    mma_gemm7<<<dim3(DIM / 128, TOKENS / 128), 256, G7_SMEM>>>(
        oh, ol, wph, out, b_proj, DIM, DIM, 0);
}

// round 15
// speedup vs baseline: 1.3118x; 1.3118x over previous
#include <cuda_runtime.h>
#include <cuda_fp16.h>
#include <stdint.h>
#include <math.h>

typedef unsigned int u32;

#define TOKENS 4096
#define DIM    1024
#define QKV_N  3072
#define NH     16
#define HD     64
#define TSEQ   2048
#define BHEADS 32
// 0.125 * log2(e)
#define SCALE2 0.18033688011112042f

// ---------------- global scratch ----------------
__device__ float2 g_trig[TSEQ * 32];

// GEMM A operands: [M][K2] u32 (fp16 pairs along K), rounded single
__device__ u32 g_xh[TOKENS * DIM / 2];
__device__ u32 g_oh2[TOKENS * DIM / 2];
// GEMM B operands: [K2][N] u32 (fp16 pairs along K), rounded single
__device__ u32 g_wqh[DIM / 2 * QKV_N];
__device__ u32 g_wph[DIM / 2 * DIM];

// flash operands: Q split hi/lo, K/V rounded single (fp16 pairs)
__device__ u32 g_qh[BHEADS * TSEQ * 32], g_ql[BHEADS * TSEQ * 32];
__device__ u32 g_kh[BHEADS * TSEQ * 32];
__device__ u32 g_vth[BHEADS * HD * (TSEQ / 2)];

// ---------------- helpers ----------------
__device__ __forceinline__ void mma_f16(float c[4],
                                        const u32 a[4], const u32 b[2])
{
    asm volatile(
        "mma.sync.aligned.m16n8k16.row.col.f32.f16.f16.f32 "
        "{%0,%1,%2,%3}, {%4,%5,%6,%7}, {%8,%9}, {%0,%1,%2,%3};"
        : "+f"(c[0]), "+f"(c[1]), "+f"(c[2]), "+f"(c[3])
        : "r"(a[0]), "r"(a[1]), "r"(a[2]), "r"(a[3]),
          "r"(b[0]), "r"(b[1]));
}

__device__ __forceinline__ void ldsm_x4(u32 r[4], u32 saddr)
{
    asm volatile(
        "ldmatrix.sync.aligned.m8n8.x4.shared.b16 {%0,%1,%2,%3}, [%4];"
        : "=r"(r[0]), "=r"(r[1]), "=r"(r[2]), "=r"(r[3]) : "r"(saddr));
}

__device__ __forceinline__ void split_pack_f16(float x0, float x1,
                                               u32& hi, u32& lo)
{
    __half2 H = __floats2half2_rn(x0, x1);
    float2 hf = __half22float2(H);
    __half2 L = __floats2half2_rn(x0 - hf.x, x1 - hf.y);
    hi = *(u32*)&H;
    lo = *(u32*)&L;
}

__device__ __forceinline__ u32 pack_f16(float x0, float x1)
{
    __half2 H = __floats2half2_rn(x0, x1);
    return *(u32*)&H;
}

// FFMA-only exp2 (no MUFU)
__device__ __forceinline__ float exp2_fast(float x)
{
    x = fmaxf(x, -60.0f);
    float t  = __fadd_rn(x, 12582912.0f);
    int   n  = __float_as_int(t) << 23;
    float ni = __fadd_rn(t, -12582912.0f);
    float r  = __fadd_rn(x, -ni);
    float p  = 1.3333558e-3f;
    p = fmaf(p, r, 9.6181291e-3f);
    p = fmaf(p, r, 5.5504109e-2f);
    p = fmaf(p, r, 2.4022651e-1f);
    p = fmaf(p, r, 6.9314718e-1f);
    p = fmaf(p, r, 1.0f);
    return __int_as_float(__float_as_int(p) + n);
}

__device__ __forceinline__ void cp16(u32* smem_dst, const u32* gsrc)
{
    unsigned d = (unsigned)__cvta_generic_to_shared(smem_dst);
    asm volatile("cp.async.cg.shared.global [%0], [%1], 16;" :: "r"(d), "l"(gsrc));
}

// ---------------- prepass kernels ----------------
__global__ __launch_bounds__(256)
void pack_pairs_rows(const float* __restrict__ src, u32* __restrict__ hi,
                     int npairs)
{
    int i = blockIdx.x * 256 + threadIdx.x;
    if (i >= npairs) return;
    float2 v = ((const float2*)src)[i];
    hi[i] = pack_f16(v.x, v.y);
}

__global__ __launch_bounds__(256)
void pack_pairs_cols(const float* __restrict__ B, u32* __restrict__ hi,
                     int N, int K)
{
    int i = blockIdx.x * 256 + threadIdx.x;
    int K2 = K >> 1;
    if (i >= K2 * N) return;
    int k2 = i / N, n = i - k2 * N;
    hi[i] = pack_f16(B[(size_t)(2 * k2) * N + n],
                     B[(size_t)(2 * k2 + 1) * N + n]);
}

__global__ __launch_bounds__(256)
void trig_table()
{
    int idx = blockIdx.x * 256 + threadIdx.x;
    if (idx >= TSEQ * 32) return;
    int t = idx >> 5, i = idx & 31;
    float freq = expf(-9.210340371976184f * (float)i * (1.0f / 32.0f));
    float ang = (float)t * freq;
    float s, c;
    sincosf(ang, &s, &c);
    g_trig[idx] = make_float2(s, c);
}

// ---------------------------------------------------------------------------
// mma_gemm8: single-pass fp16 GEMM (both operands rounded), 3-stage cp.async,
// ldmatrix A-frags. epi=0: C=A@B+bias. epi=1: fused rope/pack -> q/k/v.
// ---------------------------------------------------------------------------
#define A_ST  (128 * 20)
#define B_ST  (16 * 136)
#define STG_U32 (A_ST + B_ST)              // 4736
#define G8_SMEM (128 * 129 * 4)            // 66048 B >= 3*STG_U32*4 = 56832

__global__ __launch_bounds__(256, 2)
void mma_gemm8(const u32* __restrict__ Agh, const u32* __restrict__ Bgh,
               float* __restrict__ C, const float* __restrict__ bias,
               int N, int K, int epi)
{
    extern __shared__ u32 sm8[];

    const int tid  = threadIdx.x;
    const int wid  = tid >> 5;
    const int lane = tid & 31;
    const int r8   = lane >> 2;
    const int c4   = lane & 3;
    const int grp  = lane >> 3;
    const int wtn  = lane & 7;
    const int wm   = (wid >> 2) * 64;
    const int wn   = (wid & 3) * 32;
    const int brow = blockIdx.y, bcol = blockIdx.x;
    const int K2   = K >> 1;

    const u32 smbase = (u32)__cvta_generic_to_shared(sm8);
    const u32 lmA = (u32)(((grp & 1) * 8 + wtn) * 20 + (grp >> 1) * 4);

    const int ar  = tid & 127;
    const int acb = (tid >> 7) * 8;
    const u32* Aph = Agh + (size_t)(brow * 128 + ar) * K2 + acb;
    const int bk  = tid >> 4;
    const int bnc = (tid & 15) * 8;
    const u32* Bph = Bgh + (size_t)bk * N + bcol * 128 + bnc;

    float acc[4][4][4];
    #pragma unroll
    for (int i = 0; i < 4; i++)
        #pragma unroll
        for (int j = 0; j < 4; j++)
            #pragma unroll
            for (int r = 0; r < 4; r++) acc[i][j][r] = 0.f;

    auto issue = [&](int k2base, int s) {
        u32* st = sm8 + s * STG_U32;
        u32* aH = st + ar * 20 + acb;
        cp16(aH,     Aph + k2base);
        cp16(aH + 4, Aph + k2base + 4);
        u32* bH = st + A_ST + bk * 136 + bnc;
        cp16(bH,     Bph + (size_t)k2base * N);
        cp16(bH + 4, Bph + (size_t)k2base * N + 4);
        asm volatile("cp.async.commit_group;");
    };

    issue(0, 0);
    issue(16, 1);

    const int nst = K2 >> 4;
    int s = 0;
    for (int ks = 0; ks < nst; ks++) {
        asm volatile("cp.async.wait_group 1;");
        __syncthreads();
        if (ks + 2 < nst) {
            int s2 = s + 2; if (s2 >= 3) s2 -= 3;
            issue((ks + 2) * 16, s2);
        } else {
            asm volatile("cp.async.commit_group;");
        }

        const u32 stoff = (u32)(s * STG_U32);
        const u32 aHb = smbase + (stoff + lmA + wm * 20) * 4;
        const u32* bH = sm8 + stoff + A_ST;

        #pragma unroll
        for (int kk = 0; kk < 2; kk++) {
            const int kc = kk * 8 + c4;
            u32 bh[4][2];
            #pragma unroll
            for (int nf = 0; nf < 4; nf++) {
                const int n = wn + nf * 8 + r8;
                bh[nf][0] = bH[kc * 136 + n];
                bh[nf][1] = bH[(kc + 4) * 136 + n];
            }
            #pragma unroll
            for (int mf = 0; mf < 4; mf++) {
                u32 ah[4];
                const u32 moff = (u32)(mf * 16 * 20 + kk * 8) * 4;
                ldsm_x4(ah, aHb + moff);
                #pragma unroll
                for (int nf = 0; nf < 4; nf++)
                    mma_f16(acc[mf][nf], ah, bh[nf]);
            }
        }
        if (++s >= 3) s -= 3;
    }

    if (!epi) {
        #pragma unroll
        for (int nf = 0; nf < 4; nf++) {
            const int cg = bcol * 128 + wn + nf * 8 + c4 * 2;
            float bx = bias ? bias[cg]     : 0.f;
            float by = bias ? bias[cg + 1] : 0.f;
            #pragma unroll
            for (int mf = 0; mf < 4; mf++) {
                const int rg = brow * 128 + wm + mf * 16 + r8;
                float2 v0 = make_float2(acc[mf][nf][0] + bx, acc[mf][nf][1] + by);
                float2 v1 = make_float2(acc[mf][nf][2] + bx, acc[mf][nf][3] + by);
                *(float2*)(C + (size_t)rg * N + cg)       = v0;
                *(float2*)(C + (size_t)(rg + 8) * N + cg) = v1;
            }
        }
    } else {
        // ---- fused epilogue: stage tile in smem, rope/pack/scatter ----
        asm volatile("cp.async.wait_group 0;" ::: "memory");
        __syncthreads();
        float* S = (float*)sm8;   // [128][129]
        #pragma unroll
        for (int nf = 0; nf < 4; nf++) {
            const int cg = wn + nf * 8 + c4 * 2;
            #pragma unroll
            for (int mf = 0; mf < 4; mf++) {
                const int rg = wm + mf * 16 + r8;
                S[rg * 129 + cg]           = acc[mf][nf][0];
                S[rg * 129 + cg + 1]       = acc[mf][nf][1];
                S[(rg + 8) * 129 + cg]     = acc[mf][nf][2];
                S[(rg + 8) * 129 + cg + 1] = acc[mf][nf][3];
            }
        }
        __syncthreads();

        const int which = bcol >> 3;     // 0=q 1=k 2=v
        const int b     = brow >> 4;
        if (which < 2) {
            for (int uu = 0; uu < 32; uu++) {
                const int u    = wid * 32 + uu;
                const int head = u >> 7;
                const int row  = u & 127;
                const int tt   = (brow & 15) * 128 + row;
                const int h    = (bcol & 7) * 2 + head;
                const int bh   = b * 16 + h;
                const float* Sr = S + row * 129 + head * 64;
                const int i = lane;
                const int j = (i < 16) ? 2 * i : 2 * i - 32;
                float4 tc = *(const float4*)(&g_trig[tt * 32 + j]); // s0,c0,s1,c1
                float a0 = Sr[j],      a1 = Sr[j + 1];
                float b0 = Sr[j + 32], b1 = Sr[j + 33];
                float e0, e1;
                if (i < 16) {
                    e0 = a0 * tc.y - b0 * tc.x;
                    e1 = a1 * tc.w - b1 * tc.z;
                } else {
                    e0 = a0 * tc.x + b0 * tc.y;
                    e1 = a1 * tc.z + b1 * tc.w;
                }
                size_t po = ((size_t)bh * TSEQ + tt) * 32 + i;
                if (which == 0) {
                    u32 hi, lo;
                    split_pack_f16(e0 * SCALE2, e1 * SCALE2, hi, lo);
                    g_qh[po] = hi;
                    g_ql[po] = lo;
                } else {
                    g_kh[po] = pack_f16(e0, e1);
                }
            }
        } else {
            const int dq  = tid >> 6;
            const int t2l = tid & 63;
            const int t2g = (brow & 15) * 64 + t2l;
            #pragma unroll 4
            for (int dd = dq; dd < 128; dd += 4) {
                const int h  = (bcol & 7) * 2 + (dd >> 6);
                const int bh = b * 16 + h;
                u32 pv = pack_f16(S[(2 * t2l) * 129 + dd],
                                  S[(2 * t2l + 1) * 129 + dd]);
                g_vth[((size_t)bh * HD + (dd & 63)) * (TSEQ / 2) + t2g] = pv;
            }
        }
    }
}

// ---------------------------------------------------------------------------
// Flash attention: fp16 (Q split 2-pass S, P single-pass PV), ldmatrix,
// cp.async double-buffered, exp2 softmax. Epilogue writes packed o directly.
// ---------------------------------------------------------------------------
#define FKS  36
#define FTILE (64 * FKS)

__global__ __launch_bounds__(256)
void flash_mma()
{
    __shared__ u32 Ksh[2 * FTILE];
    __shared__ u32 Vsh[2 * FTILE];

    const int bh   = blockIdx.y;
    const int qblk = gridDim.x - 1 - blockIdx.x;
    const int q0   = qblk * 128;

    const int tid  = threadIdx.x;
    const int w    = tid >> 5;
    const int lane = tid & 31;
    const int r8   = lane >> 2;
    const int c4   = lane & 3;
    const int grp  = lane >> 3;
    const int wtn  = lane & 7;

    const u32 Kbase = (u32)__cvta_generic_to_shared(Ksh);
    const u32 Vbase = (u32)__cvta_generic_to_shared(Vsh);
    const u32 lmF = (u32)(((grp >> 1) * 8 + wtn) * FKS + (grp & 1) * 4);

    u32 qh[4][4], ql[4][4];
    {
        const u32* Qh = g_qh + ((size_t)bh * TSEQ + q0 + w * 16) * 32;
        const u32* Ql = g_ql + ((size_t)bh * TSEQ + q0 + w * 16) * 32;
        #pragma unroll
        for (int g = 0; g < 4; g++) {
            qh[g][0] = Qh[(size_t)r8 * 32 + 8 * g + c4];
            qh[g][1] = Qh[(size_t)(r8 + 8) * 32 + 8 * g + c4];
            qh[g][2] = Qh[(size_t)r8 * 32 + 8 * g + c4 + 4];
            qh[g][3] = Qh[(size_t)(r8 + 8) * 32 + 8 * g + c4 + 4];
            ql[g][0] = Ql[(size_t)r8 * 32 + 8 * g + c4];
            ql[g][1] = Ql[(size_t)(r8 + 8) * 32 + 8 * g + c4];
            ql[g][2] = Ql[(size_t)r8 * 32 + 8 * g + c4 + 4];
            ql[g][3] = Ql[(size_t)(r8 + 8) * 32 + 8 * g + c4 + 4];
        }
    }

    float oacc[8][4];
    #pragma unroll
    for (int i = 0; i < 8; i++)
        #pragma unroll
        for (int j = 0; j < 4; j++) oacc[i][j] = 0.f;
    float m0 = -1e30f, m1 = -1e30f, l0 = 0.f, l1 = 0.f;

    const int row0 = q0 + w * 16 + r8;
    const int row1 = row0 + 8;

    const u32* Kgh = g_kh + (size_t)bh * TSEQ * 32;
    const u32* Vgh = g_vth + (size_t)bh * HD * (TSEQ / 2);

    const int lr = tid >> 2, lcb = (tid & 3) * 8;

    auto fissue = [&](int tile, int s) {
        const int k0 = tile * 64;
        const u32* kh = Kgh + (size_t)(k0 + lr) * 32 + lcb;
        const u32* vh = Vgh + (size_t)lr * (TSEQ / 2) + (k0 >> 1) + lcb;
        u32* dk = Ksh + s * FTILE + lr * FKS + lcb;
        u32* dv = Vsh + s * FTILE + lr * FKS + lcb;
        cp16(dk,     kh);
        cp16(dk + 4, kh + 4);
        cp16(dv,     vh);
        cp16(dv + 4, vh + 4);
        asm volatile("cp.async.commit_group;");
    };

    const int ntiles = 2 * qblk + 2;
    fissue(0, 0);

    for (int tile = 0; tile < ntiles; tile++) {
        asm volatile("cp.async.wait_group 0;");
        __syncthreads();
        if (tile + 1 < ntiles) fissue(tile + 1, (tile + 1) & 1);

        const u32 sboff = (u32)((tile & 1) * FTILE);
        const int k0 = tile * 64;

        const bool active = (k0 <= q0 + w * 16 + 15);
        if (active) {
            float sacc[8][4];
            #pragma unroll
            for (int i = 0; i < 8; i++)
                #pragma unroll
                for (int j = 0; j < 4; j++) sacc[i][j] = 0.f;

            const u32 kfb = Kbase + (sboff + lmF) * 4;
            #pragma unroll
            for (int g = 0; g < 4; g++) {
                #pragma unroll
                for (int nfp = 0; nfp < 4; nfp++) {
                    u32 kf[4];
                    ldsm_x4(kf, kfb + (u32)(nfp * 16 * FKS + 8 * g) * 4);
                    mma_f16(sacc[2 * nfp],     qh[g], kf);
                    mma_f16(sacc[2 * nfp],     ql[g], kf);
                    mma_f16(sacc[2 * nfp + 1], qh[g], kf + 2);
                    mma_f16(sacc[2 * nfp + 1], ql[g], kf + 2);
                }
            }

            if (k0 + 63 > row0) {
                #pragma unroll
                for (int nf = 0; nf < 8; nf++) {
                    const int n0 = k0 + nf * 8 + 2 * c4;
                    if (n0 > row0)     sacc[nf][0] = -1e30f;
                    if (n0 + 1 > row0) sacc[nf][1] = -1e30f;
                    if (n0 > row1)     sacc[nf][2] = -1e30f;
                    if (n0 + 1 > row1) sacc[nf][3] = -1e30f;
                }
            }

            float rm0 = -1e30f, rm1 = -1e30f;
            #pragma unroll
            for (int nf = 0; nf < 8; nf++) {
                rm0 = fmaxf(rm0, fmaxf(sacc[nf][0], sacc[nf][1]));
                rm1 = fmaxf(rm1, fmaxf(sacc[nf][2], sacc[nf][3]));
            }
            rm0 = fmaxf(rm0, __shfl_xor_sync(0xffffffffu, rm0, 1));
            rm0 = fmaxf(rm0, __shfl_xor_sync(0xffffffffu, rm0, 2));
            rm1 = fmaxf(rm1, __shfl_xor_sync(0xffffffffu, rm1, 1));
            rm1 = fmaxf(rm1, __shfl_xor_sync(0xffffffffu, rm1, 2));

            const float mn0 = fmaxf(m0, rm0);
            const float mn1 = fmaxf(m1, rm1);
            const float rs0 = exp2_fast(m0 - mn0);
            const float rs1 = exp2_fast(m1 - mn1);
            m0 = mn0; m1 = mn1;

            float sum0 = 0.f, sum1 = 0.f;
            #pragma unroll
            for (int nf = 0; nf < 8; nf++) {
                sacc[nf][0] = exp2_fast(sacc[nf][0] - mn0);
                sacc[nf][1] = exp2_fast(sacc[nf][1] - mn0);
                sacc[nf][2] = exp2_fast(sacc[nf][2] - mn1);
                sacc[nf][3] = exp2_fast(sacc[nf][3] - mn1);
                sum0 += sacc[nf][0] + sacc[nf][1];
                sum1 += sacc[nf][2] + sacc[nf][3];
            }
            sum0 += __shfl_xor_sync(0xffffffffu, sum0, 1);
            sum0 += __shfl_xor_sync(0xffffffffu, sum0, 2);
            sum1 += __shfl_xor_sync(0xffffffffu, sum1, 1);
            sum1 += __shfl_xor_sync(0xffffffffu, sum1, 2);
            l0 = l0 * rs0 + sum0;
            l1 = l1 * rs1 + sum1;

            #pragma unroll
            for (int nf = 0; nf < 8; nf++) {
                oacc[nf][0] *= rs0;
                oacc[nf][1] *= rs0;
                oacc[nf][2] *= rs1;
                oacc[nf][3] *= rs1;
            }

            const u32 vfb = Vbase + (sboff + lmF) * 4;
            #pragma unroll
            for (int g = 0; g < 4; g++) {
                u32 ph[4];
                ph[0] = pack_f16(sacc[2 * g][0],     sacc[2 * g][1]);
                ph[1] = pack_f16(sacc[2 * g][2],     sacc[2 * g][3]);
                ph[2] = pack_f16(sacc[2 * g + 1][0], sacc[2 * g + 1][1]);
                ph[3] = pack_f16(sacc[2 * g + 1][2], sacc[2 * g + 1][3]);
                #pragma unroll
                for (int nfp = 0; nfp < 4; nfp++) {
                    u32 vf[4];
                    ldsm_x4(vf, vfb + (u32)(nfp * 16 * FKS + 8 * g) * 4);
                    mma_f16(oacc[2 * nfp],     ph, vf);
                    mma_f16(oacc[2 * nfp + 1], ph, vf + 2);
                }
            }
        }
    }

    // epilogue: normalize and write packed fp16 o directly (proj A-operand)
    const float inv0 = 1.0f / l0;
    const float inv1 = 1.0f / l1;
    const int b = bh >> 4, h = bh & 15;
    #pragma unroll
    for (int nf = 0; nf < 8; nf++) {
        const size_t i0 = ((size_t)(b * TSEQ) + row0) * 512 + h * 32 + nf * 4 + c4;
        const size_t i1 = ((size_t)(b * TSEQ) + row1) * 512 + h * 32 + nf * 4 + c4;
        g_oh2[i0] = pack_f16(oacc[nf][0] * inv0, oacc[nf][1] * inv0);
        g_oh2[i1] = pack_f16(oacc[nf][2] * inv1, oacc[nf][3] * inv1);
    }
}

// ---------------------------------------------------------------------------
extern "C" void kernel_launch(void* const* d_in, const int* in_sizes, int n_in,
                              void* d_out, int out_size)
{
    const float* x      = (const float*)d_in[0];
    const float* w_qkv  = (const float*)d_in[1];
    const float* w_proj = (const float*)d_in[2];
    const float* b_proj = (const float*)d_in[3];
    float* out = (float*)d_out;

    u32 *xh, *oh, *wqh, *wph;
    cudaGetSymbolAddress((void**)&xh,  g_xh);
    cudaGetSymbolAddress((void**)&oh,  g_oh2);
    cudaGetSymbolAddress((void**)&wqh, g_wqh);
    cudaGetSymbolAddress((void**)&wph, g_wph);

    cudaFuncSetAttribute(mma_gemm8,
                         cudaFuncAttributeMaxDynamicSharedMemorySize, G8_SMEM);

    // 0) trig table + operand prepasses
    trig_table<<<(TSEQ * 32 + 255) / 256, 256>>>();
    const int xpairs = TOKENS * DIM / 2;
    pack_pairs_rows<<<(xpairs + 255) / 256, 256>>>(x, xh, xpairs);
    pack_pairs_cols<<<((DIM / 2) * QKV_N + 255) / 256, 256>>>(w_qkv, wqh, QKV_N, DIM);
    pack_pairs_cols<<<((DIM / 2) * DIM + 255) / 256, 256>>>(w_proj, wph, DIM, DIM);

    // 1) qkv = x @ w_qkv -> fused rope/pack -> g_qh/g_ql/g_kh/g_vth
    mma_gemm8<<<dim3(QKV_N / 128, TOKENS / 128), 256, G8_SMEM>>>(
        xh, wqh, nullptr, nullptr, QKV_N, DIM, 1);

    // 2) flash attention (writes packed o directly)
    flash_mma<<<dim3(TSEQ / 128, BHEADS), 256>>>();

    // 3) out = o @ w_proj + b_proj
    mma_gemm8<<<dim3(DIM / 128, TOKENS / 128), 256, G8_SMEM>>>(
        oh, wph, out, b_proj, DIM, DIM, 0);
}

// round 16
// speedup vs baseline: 1.4652x; 1.1169x over previous
#include <cuda_runtime.h>
#include <cuda_fp16.h>
#include <stdint.h>
#include <math.h>

typedef unsigned int u32;

#define TOKENS 4096
#define DIM    1024
#define QKV_N  3072
#define NH     16
#define HD     64
#define TSEQ   2048
#define BHEADS 32
// 0.125 * log2(e)
#define SCALE2 0.18033688011112042f

// ---------------- global scratch ----------------
__device__ float2 g_trig[TSEQ * 32];

// GEMM A operands: [M][K2] u32 (fp16 pairs along K), rounded single
__device__ u32 g_xh[TOKENS * DIM / 2];
__device__ u32 g_oh2[TOKENS * DIM / 2];
// GEMM B operands: [K2][N] u32 (fp16 pairs along K), rounded single
__device__ u32 g_wqh[DIM / 2 * QKV_N];
__device__ u32 g_wph[DIM / 2 * DIM];

// flash operands: all rounded single fp16 pairs
__device__ u32 g_qh[BHEADS * TSEQ * 32];
__device__ u32 g_kh[BHEADS * TSEQ * 32];
__device__ u32 g_vth[BHEADS * HD * (TSEQ / 2)];

// ---------------- helpers ----------------
__device__ __forceinline__ void mma_f16(float c[4],
                                        const u32 a[4], const u32 b[2])
{
    asm volatile(
        "mma.sync.aligned.m16n8k16.row.col.f32.f16.f16.f32 "
        "{%0,%1,%2,%3}, {%4,%5,%6,%7}, {%8,%9}, {%0,%1,%2,%3};"
        : "+f"(c[0]), "+f"(c[1]), "+f"(c[2]), "+f"(c[3])
        : "r"(a[0]), "r"(a[1]), "r"(a[2]), "r"(a[3]),
          "r"(b[0]), "r"(b[1]));
}

__device__ __forceinline__ void ldsm_x4(u32 r[4], u32 saddr)
{
    asm volatile(
        "ldmatrix.sync.aligned.m8n8.x4.shared.b16 {%0,%1,%2,%3}, [%4];"
        : "=r"(r[0]), "=r"(r[1]), "=r"(r[2]), "=r"(r[3]) : "r"(saddr));
}

__device__ __forceinline__ u32 pack_f16(float x0, float x1)
{
    __half2 H = __floats2half2_rn(x0, x1);
    return *(u32*)&H;
}

// FFMA-only exp2 (no MUFU)
__device__ __forceinline__ float exp2_fast(float x)
{
    x = fmaxf(x, -60.0f);
    float t  = __fadd_rn(x, 12582912.0f);
    int   n  = __float_as_int(t) << 23;
    float ni = __fadd_rn(t, -12582912.0f);
    float r  = __fadd_rn(x, -ni);
    float p  = 1.3333558e-3f;
    p = fmaf(p, r, 9.6181291e-3f);
    p = fmaf(p, r, 5.5504109e-2f);
    p = fmaf(p, r, 2.4022651e-1f);
    p = fmaf(p, r, 6.9314718e-1f);
    p = fmaf(p, r, 1.0f);
    return __int_as_float(__float_as_int(p) + n);
}

__device__ __forceinline__ void cp16(u32* smem_dst, const u32* gsrc)
{
    unsigned d = (unsigned)__cvta_generic_to_shared(smem_dst);
    asm volatile("cp.async.cg.shared.global [%0], [%1], 16;" :: "r"(d), "l"(gsrc));
}

// ---------------- prepass kernels ----------------
__global__ __launch_bounds__(256)
void pack_pairs_rows(const float* __restrict__ src, u32* __restrict__ hi,
                     int npairs)
{
    int i = blockIdx.x * 256 + threadIdx.x;
    if (i >= npairs) return;
    float2 v = ((const float2*)src)[i];
    hi[i] = pack_f16(v.x, v.y);
}

__global__ __launch_bounds__(256)
void pack_pairs_cols(const float* __restrict__ B, u32* __restrict__ hi,
                     int N, int K)
{
    int i = blockIdx.x * 256 + threadIdx.x;
    int K2 = K >> 1;
    if (i >= K2 * N) return;
    int k2 = i / N, n = i - k2 * N;
    hi[i] = pack_f16(B[(size_t)(2 * k2) * N + n],
                     B[(size_t)(2 * k2 + 1) * N + n]);
}

__global__ __launch_bounds__(256)
void trig_table()
{
    int idx = blockIdx.x * 256 + threadIdx.x;
    if (idx >= TSEQ * 32) return;
    int t = idx >> 5, i = idx & 31;
    float freq = expf(-9.210340371976184f * (float)i * (1.0f / 32.0f));
    float ang = (float)t * freq;
    float s, c;
    sincosf(ang, &s, &c);
    g_trig[idx] = make_float2(s, c);
}

// ---------------------------------------------------------------------------
// mma_gemm8: single-pass fp16 GEMM, 3-stage cp.async, ldmatrix A-frags.
// epi=0: C=A@B+bias. epi=1: fused rope/pack -> q/k/v.
// ---------------------------------------------------------------------------
#define A_ST  (128 * 20)
#define B_ST  (16 * 136)
#define STG_U32 (A_ST + B_ST)              // 4736
#define G8_SMEM (128 * 129 * 4)            // 66048 B >= 3*STG_U32*4 = 56832

__global__ __launch_bounds__(256, 2)
void mma_gemm8(const u32* __restrict__ Agh, const u32* __restrict__ Bgh,
               float* __restrict__ C, const float* __restrict__ bias,
               int N, int K, int epi)
{
    extern __shared__ u32 sm8[];

    const int tid  = threadIdx.x;
    const int wid  = tid >> 5;
    const int lane = tid & 31;
    const int r8   = lane >> 2;
    const int c4   = lane & 3;
    const int grp  = lane >> 3;
    const int wtn  = lane & 7;
    const int wm   = (wid >> 2) * 64;
    const int wn   = (wid & 3) * 32;
    const int brow = blockIdx.y, bcol = blockIdx.x;
    const int K2   = K >> 1;

    const u32 smbase = (u32)__cvta_generic_to_shared(sm8);
    const u32 lmA = (u32)(((grp & 1) * 8 + wtn) * 20 + (grp >> 1) * 4);

    const int ar  = tid & 127;
    const int acb = (tid >> 7) * 8;
    const u32* Aph = Agh + (size_t)(brow * 128 + ar) * K2 + acb;
    const int bk  = tid >> 4;
    const int bnc = (tid & 15) * 8;
    const u32* Bph = Bgh + (size_t)bk * N + bcol * 128 + bnc;

    float acc[4][4][4];
    #pragma unroll
    for (int i = 0; i < 4; i++)
        #pragma unroll
        for (int j = 0; j < 4; j++)
            #pragma unroll
            for (int r = 0; r < 4; r++) acc[i][j][r] = 0.f;

    auto issue = [&](int k2base, int s) {
        u32* st = sm8 + s * STG_U32;
        u32* aH = st + ar * 20 + acb;
        cp16(aH,     Aph + k2base);
        cp16(aH + 4, Aph + k2base + 4);
        u32* bH = st + A_ST + bk * 136 + bnc;
        cp16(bH,     Bph + (size_t)k2base * N);
        cp16(bH + 4, Bph + (size_t)k2base * N + 4);
        asm volatile("cp.async.commit_group;");
    };

    issue(0, 0);
    issue(16, 1);

    const int nst = K2 >> 4;
    int s = 0;
    for (int ks = 0; ks < nst; ks++) {
        asm volatile("cp.async.wait_group 1;");
        __syncthreads();
        if (ks + 2 < nst) {
            int s2 = s + 2; if (s2 >= 3) s2 -= 3;
            issue((ks + 2) * 16, s2);
        } else {
            asm volatile("cp.async.commit_group;");
        }

        const u32 stoff = (u32)(s * STG_U32);
        const u32 aHb = smbase + (stoff + lmA + wm * 20) * 4;
        const u32* bH = sm8 + stoff + A_ST;

        #pragma unroll
        for (int kk = 0; kk < 2; kk++) {
            const int kc = kk * 8 + c4;
            u32 bh[4][2];
            #pragma unroll
            for (int nf = 0; nf < 4; nf++) {
                const int n = wn + nf * 8 + r8;
                bh[nf][0] = bH[kc * 136 + n];
                bh[nf][1] = bH[(kc + 4) * 136 + n];
            }
            #pragma unroll
            for (int mf = 0; mf < 4; mf++) {
                u32 ah[4];
                const u32 moff = (u32)(mf * 16 * 20 + kk * 8) * 4;
                ldsm_x4(ah, aHb + moff);
                #pragma unroll
                for (int nf = 0; nf < 4; nf++)
                    mma_f16(acc[mf][nf], ah, bh[nf]);
            }
        }
        if (++s >= 3) s -= 3;
    }

    if (!epi) {
        #pragma unroll
        for (int nf = 0; nf < 4; nf++) {
            const int cg = bcol * 128 + wn + nf * 8 + c4 * 2;
            float bx = bias ? bias[cg]     : 0.f;
            float by = bias ? bias[cg + 1] : 0.f;
            #pragma unroll
            for (int mf = 0; mf < 4; mf++) {
                const int rg = brow * 128 + wm + mf * 16 + r8;
                float2 v0 = make_float2(acc[mf][nf][0] + bx, acc[mf][nf][1] + by);
                float2 v1 = make_float2(acc[mf][nf][2] + bx, acc[mf][nf][3] + by);
                *(float2*)(C + (size_t)rg * N + cg)       = v0;
                *(float2*)(C + (size_t)(rg + 8) * N + cg) = v1;
            }
        }
    } else {
        // ---- fused epilogue: stage tile in smem, rope/pack/scatter ----
        asm volatile("cp.async.wait_group 0;" ::: "memory");
        __syncthreads();
        float* S = (float*)sm8;   // [128][129]
        #pragma unroll
        for (int nf = 0; nf < 4; nf++) {
            const int cg = wn + nf * 8 + c4 * 2;
            #pragma unroll
            for (int mf = 0; mf < 4; mf++) {
                const int rg = wm + mf * 16 + r8;
                S[rg * 129 + cg]           = acc[mf][nf][0];
                S[rg * 129 + cg + 1]       = acc[mf][nf][1];
                S[(rg + 8) * 129 + cg]     = acc[mf][nf][2];
                S[(rg + 8) * 129 + cg + 1] = acc[mf][nf][3];
            }
        }
        __syncthreads();

        const int which = bcol >> 3;     // 0=q 1=k 2=v
        const int b     = brow >> 4;
        if (which < 2) {
            for (int uu = 0; uu < 32; uu++) {
                const int u    = wid * 32 + uu;
                const int head = u >> 7;
                const int row  = u & 127;
                const int tt   = (brow & 15) * 128 + row;
                const int h    = (bcol & 7) * 2 + head;
                const int bh   = b * 16 + h;
                const float* Sr = S + row * 129 + head * 64;
                const int i = lane;
                const int j = (i < 16) ? 2 * i : 2 * i - 32;
                float4 tc = *(const float4*)(&g_trig[tt * 32 + j]); // s0,c0,s1,c1
                float a0 = Sr[j],      a1 = Sr[j + 1];
                float b0 = Sr[j + 32], b1 = Sr[j + 33];
                float e0, e1;
                if (i < 16) {
                    e0 = a0 * tc.y - b0 * tc.x;
                    e1 = a1 * tc.w - b1 * tc.z;
                } else {
                    e0 = a0 * tc.x + b0 * tc.y;
                    e1 = a1 * tc.z + b1 * tc.w;
                }
                size_t po = ((size_t)bh * TSEQ + tt) * 32 + i;
                if (which == 0) {
                    g_qh[po] = pack_f16(e0 * SCALE2, e1 * SCALE2);
                } else {
                    g_kh[po] = pack_f16(e0, e1);
                }
            }
        } else {
            const int dq  = tid >> 6;
            const int t2l = tid & 63;
            const int t2g = (brow & 15) * 64 + t2l;
            #pragma unroll 4
            for (int dd = dq; dd < 128; dd += 4) {
                const int h  = (bcol & 7) * 2 + (dd >> 6);
                const int bh = b * 16 + h;
                u32 pv = pack_f16(S[(2 * t2l) * 129 + dd],
                                  S[(2 * t2l + 1) * 129 + dd]);
                g_vth[((size_t)bh * HD + (dd & 63)) * (TSEQ / 2) + t2g] = pv;
            }
        }
    }
}

// ---------------------------------------------------------------------------
// Flash attention: fp16 single-pass S and PV, ldmatrix, cp.async double-
// buffered, exp2 softmax. Epilogue writes packed o directly.
// ---------------------------------------------------------------------------
#define FKS  36
#define FTILE (64 * FKS)

__global__ __launch_bounds__(256)
void flash_mma()
{
    __shared__ u32 Ksh[2 * FTILE];
    __shared__ u32 Vsh[2 * FTILE];

    const int bh   = blockIdx.y;
    const int qblk = gridDim.x - 1 - blockIdx.x;
    const int q0   = qblk * 128;

    const int tid  = threadIdx.x;
    const int w    = tid >> 5;
    const int lane = tid & 31;
    const int r8   = lane >> 2;
    const int c4   = lane & 3;
    const int grp  = lane >> 3;
    const int wtn  = lane & 7;

    const u32 Kbase = (u32)__cvta_generic_to_shared(Ksh);
    const u32 Vbase = (u32)__cvta_generic_to_shared(Vsh);
    const u32 lmF = (u32)(((grp >> 1) * 8 + wtn) * FKS + (grp & 1) * 4);

    u32 qh[4][4];
    {
        const u32* Qh = g_qh + ((size_t)bh * TSEQ + q0 + w * 16) * 32;
        #pragma unroll
        for (int g = 0; g < 4; g++) {
            qh[g][0] = Qh[(size_t)r8 * 32 + 8 * g + c4];
            qh[g][1] = Qh[(size_t)(r8 + 8) * 32 + 8 * g + c4];
            qh[g][2] = Qh[(size_t)r8 * 32 + 8 * g + c4 + 4];
            qh[g][3] = Qh[(size_t)(r8 + 8) * 32 + 8 * g + c4 + 4];
        }
    }

    float oacc[8][4];
    #pragma unroll
    for (int i = 0; i < 8; i++)
        #pragma unroll
        for (int j = 0; j < 4; j++) oacc[i][j] = 0.f;
    float m0 = -1e30f, m1 = -1e30f, l0 = 0.f, l1 = 0.f;

    const int row0 = q0 + w * 16 + r8;
    const int row1 = row0 + 8;

    const u32* Kgh = g_kh + (size_t)bh * TSEQ * 32;
    const u32* Vgh = g_vth + (size_t)bh * HD * (TSEQ / 2);

    const int lr = tid >> 2, lcb = (tid & 3) * 8;

    auto fissue = [&](int tile, int s) {
        const int k0 = tile * 64;
        const u32* kh = Kgh + (size_t)(k0 + lr) * 32 + lcb;
        const u32* vh = Vgh + (size_t)lr * (TSEQ / 2) + (k0 >> 1) + lcb;
        u32* dk = Ksh + s * FTILE + lr * FKS + lcb;
        u32* dv = Vsh + s * FTILE + lr * FKS + lcb;
        cp16(dk,     kh);
        cp16(dk + 4, kh + 4);
        cp16(dv,     vh);
        cp16(dv + 4, vh + 4);
        asm volatile("cp.async.commit_group;");
    };

    const int ntiles = 2 * qblk + 2;
    fissue(0, 0);

    for (int tile = 0; tile < ntiles; tile++) {
        asm volatile("cp.async.wait_group 0;");
        __syncthreads();
        if (tile + 1 < ntiles) fissue(tile + 1, (tile + 1) & 1);

        const u32 sboff = (u32)((tile & 1) * FTILE);
        const int k0 = tile * 64;

        const bool active = (k0 <= q0 + w * 16 + 15);
        if (active) {
            float sacc[8][4];
            #pragma unroll
            for (int i = 0; i < 8; i++)
                #pragma unroll
                for (int j = 0; j < 4; j++) sacc[i][j] = 0.f;

            const u32 kfb = Kbase + (sboff + lmF) * 4;
            #pragma unroll
            for (int g = 0; g < 4; g++) {
                #pragma unroll
                for (int nfp = 0; nfp < 4; nfp++) {
                    u32 kf[4];
                    ldsm_x4(kf, kfb + (u32)(nfp * 16 * FKS + 8 * g) * 4);
                    mma_f16(sacc[2 * nfp],     qh[g], kf);
                    mma_f16(sacc[2 * nfp + 1], qh[g], kf + 2);
                }
            }

            if (k0 + 63 > row0) {
                #pragma unroll
                for (int nf = 0; nf < 8; nf++) {
                    const int n0 = k0 + nf * 8 + 2 * c4;
                    if (n0 > row0)     sacc[nf][0] = -1e30f;
                    if (n0 + 1 > row0) sacc[nf][1] = -1e30f;
                    if (n0 > row1)     sacc[nf][2] = -1e30f;
                    if (n0 + 1 > row1) sacc[nf][3] = -1e30f;
                }
            }

            float rm0 = -1e30f, rm1 = -1e30f;
            #pragma unroll
            for (int nf = 0; nf < 8; nf++) {
                rm0 = fmaxf(rm0, fmaxf(sacc[nf][0], sacc[nf][1]));
                rm1 = fmaxf(rm1, fmaxf(sacc[nf][2], sacc[nf][3]));
            }
            rm0 = fmaxf(rm0, __shfl_xor_sync(0xffffffffu, rm0, 1));
            rm0 = fmaxf(rm0, __shfl_xor_sync(0xffffffffu, rm0, 2));
            rm1 = fmaxf(rm1, __shfl_xor_sync(0xffffffffu, rm1, 1));
            rm1 = fmaxf(rm1, __shfl_xor_sync(0xffffffffu, rm1, 2));

            const float mn0 = fmaxf(m0, rm0);
            const float mn1 = fmaxf(m1, rm1);
            const float rs0 = exp2_fast(m0 - mn0);
            const float rs1 = exp2_fast(m1 - mn1);
            m0 = mn0; m1 = mn1;

            float sum0 = 0.f, sum1 = 0.f;
            #pragma unroll
            for (int nf = 0; nf < 8; nf++) {
                sacc[nf][0] = exp2_fast(sacc[nf][0] - mn0);
                sacc[nf][1] = exp2_fast(sacc[nf][1] - mn0);
                sacc[nf][2] = exp2_fast(sacc[nf][2] - mn1);
                sacc[nf][3] = exp2_fast(sacc[nf][3] - mn1);
                sum0 += sacc[nf][0] + sacc[nf][1];
                sum1 += sacc[nf][2] + sacc[nf][3];
            }
            sum0 += __shfl_xor_sync(0xffffffffu, sum0, 1);
            sum0 += __shfl_xor_sync(0xffffffffu, sum0, 2);
            sum1 += __shfl_xor_sync(0xffffffffu, sum1, 1);
            sum1 += __shfl_xor_sync(0xffffffffu, sum1, 2);
            l0 = l0 * rs0 + sum0;
            l1 = l1 * rs1 + sum1;

            #pragma unroll
            for (int nf = 0; nf < 8; nf++) {
                oacc[nf][0] *= rs0;
                oacc[nf][1] *= rs0;
                oacc[nf][2] *= rs1;
                oacc[nf][3] *= rs1;
            }

            const u32 vfb = Vbase + (sboff + lmF) * 4;
            #pragma unroll
            for (int g = 0; g < 4; g++) {
                u32 ph[4];
                ph[0] = pack_f16(sacc[2 * g][0],     sacc[2 * g][1]);
                ph[1] = pack_f16(sacc[2 * g][2],     sacc[2 * g][3]);
                ph[2] = pack_f16(sacc[2 * g + 1][0], sacc[2 * g + 1][1]);
                ph[3] = pack_f16(sacc[2 * g + 1][2], sacc[2 * g + 1][3]);
                #pragma unroll
                for (int nfp = 0; nfp < 4; nfp++) {
                    u32 vf[4];
                    ldsm_x4(vf, vfb + (u32)(nfp * 16 * FKS + 8 * g) * 4);
                    mma_f16(oacc[2 * nfp],     ph, vf);
                    mma_f16(oacc[2 * nfp + 1], ph, vf + 2);
                }
            }
        }
    }

    // epilogue: normalize and write packed fp16 o directly (proj A-operand)
    const float inv0 = 1.0f / l0;
    const float inv1 = 1.0f / l1;
    const int b = bh >> 4, h = bh & 15;
    #pragma unroll
    for (int nf = 0; nf < 8; nf++) {
        const size_t i0 = ((size_t)(b * TSEQ) + row0) * 512 + h * 32 + nf * 4 + c4;
        const size_t i1 = ((size_t)(b * TSEQ) + row1) * 512 + h * 32 + nf * 4 + c4;
        g_oh2[i0] = pack_f16(oacc[nf][0] * inv0, oacc[nf][1] * inv0);
        g_oh2[i1] = pack_f16(oacc[nf][2] * inv1, oacc[nf][3] * inv1);
    }
}

// ---------------------------------------------------------------------------
extern "C" void kernel_launch(void* const* d_in, const int* in_sizes, int n_in,
                              void* d_out, int out_size)
{
    const float* x      = (const float*)d_in[0];
    const float* w_qkv  = (const float*)d_in[1];
    const float* w_proj = (const float*)d_in[2];
    const float* b_proj = (const float*)d_in[3];
    float* out = (float*)d_out;

    u32 *xh, *oh, *wqh, *wph;
    cudaGetSymbolAddress((void**)&xh,  g_xh);
    cudaGetSymbolAddress((void**)&oh,  g_oh2);
    cudaGetSymbolAddress((void**)&wqh, g_wqh);
    cudaGetSymbolAddress((void**)&wph, g_wph);

    cudaFuncSetAttribute(mma_gemm8,
                         cudaFuncAttributeMaxDynamicSharedMemorySize, G8_SMEM);

    // 0) trig table + operand prepasses
    trig_table<<<(TSEQ * 32 + 255) / 256, 256>>>();
    const int xpairs = TOKENS * DIM / 2;
    pack_pairs_rows<<<(xpairs + 255) / 256, 256>>>(x, xh, xpairs);
    pack_pairs_cols<<<((DIM / 2) * QKV_N + 255) / 256, 256>>>(w_qkv, wqh, QKV_N, DIM);
    pack_pairs_cols<<<((DIM / 2) * DIM + 255) / 256, 256>>>(w_proj, wph, DIM, DIM);

    // 1) qkv = x @ w_qkv -> fused rope/pack -> g_qh/g_kh/g_vth
    mma_gemm8<<<dim3(QKV_N / 128, TOKENS / 128), 256, G8_SMEM>>>(
        xh, wqh, nullptr, nullptr, QKV_N, DIM, 1);

    // 2) flash attention (writes packed o directly)
    flash_mma<<<dim3(TSEQ / 128, BHEADS), 256>>>();

    // 3) out = o @ w_proj + b_proj
    mma_gemm8<<<dim3(DIM / 128, TOKENS / 128), 256, G8_SMEM>>>(
        oh, wph, out, b_proj, DIM, DIM, 0);
}

// round 17
// speedup vs baseline: 1.4743x; 1.0062x over previous
#include <cuda_runtime.h>
#include <cuda_fp16.h>
#include <stdint.h>
#include <math.h>

typedef unsigned int u32;

#define TOKENS 4096
#define DIM    1024
#define QKV_N  3072
#define NH     16
#define HD     64
#define TSEQ   2048
#define BHEADS 32
// 0.125 * log2(e)
#define SCALE2 0.18033688011112042f

// ---------------- global scratch ----------------
__device__ float2 g_trig[TSEQ * 32];

// GEMM A operands: [M][K2] u32 (fp16 pairs along K), rounded single
__device__ u32 g_xh[TOKENS * DIM / 2];
__device__ u32 g_oh2[TOKENS * DIM / 2];
// GEMM B operands: [K2][N] u32 (fp16 pairs along K), rounded single
__device__ u32 g_wqh[DIM / 2 * QKV_N];
__device__ u32 g_wph[DIM / 2 * DIM];

// flash operands: all rounded single fp16 pairs
__device__ u32 g_qh[BHEADS * TSEQ * 32];
__device__ u32 g_kh[BHEADS * TSEQ * 32];
__device__ u32 g_vth[BHEADS * HD * (TSEQ / 2)];

// ---------------- helpers ----------------
__device__ __forceinline__ void mma_f16(float c[4],
                                        const u32 a[4], const u32 b[2])
{
    asm volatile(
        "mma.sync.aligned.m16n8k16.row.col.f32.f16.f16.f32 "
        "{%0,%1,%2,%3}, {%4,%5,%6,%7}, {%8,%9}, {%0,%1,%2,%3};"
        : "+f"(c[0]), "+f"(c[1]), "+f"(c[2]), "+f"(c[3])
        : "r"(a[0]), "r"(a[1]), "r"(a[2]), "r"(a[3]),
          "r"(b[0]), "r"(b[1]));
}

__device__ __forceinline__ void ldsm_x4(u32 r[4], u32 saddr)
{
    asm volatile(
        "ldmatrix.sync.aligned.m8n8.x4.shared.b16 {%0,%1,%2,%3}, [%4];"
        : "=r"(r[0]), "=r"(r[1]), "=r"(r[2]), "=r"(r[3]) : "r"(saddr));
}

__device__ __forceinline__ u32 pack_f16(float x0, float x1)
{
    __half2 H = __floats2half2_rn(x0, x1);
    return *(u32*)&H;
}

// FFMA-only exp2 (no MUFU)
__device__ __forceinline__ float exp2_fast(float x)
{
    x = fmaxf(x, -60.0f);
    float t  = __fadd_rn(x, 12582912.0f);
    int   n  = __float_as_int(t) << 23;
    float ni = __fadd_rn(t, -12582912.0f);
    float r  = __fadd_rn(x, -ni);
    float p  = 1.3333558e-3f;
    p = fmaf(p, r, 9.6181291e-3f);
    p = fmaf(p, r, 5.5504109e-2f);
    p = fmaf(p, r, 2.4022651e-1f);
    p = fmaf(p, r, 6.9314718e-1f);
    p = fmaf(p, r, 1.0f);
    return __int_as_float(__float_as_int(p) + n);
}

__device__ __forceinline__ void cp16(u32* smem_dst, const u32* gsrc)
{
    unsigned d = (unsigned)__cvta_generic_to_shared(smem_dst);
    asm volatile("cp.async.cg.shared.global [%0], [%1], 16;" :: "r"(d), "l"(gsrc));
}

// ---------------- prepass kernels ----------------
__global__ __launch_bounds__(256)
void pack_pairs_rows(const float* __restrict__ src, u32* __restrict__ hi,
                     int npairs)
{
    int i = blockIdx.x * 256 + threadIdx.x;
    if (i >= npairs) return;
    float2 v = ((const float2*)src)[i];
    hi[i] = pack_f16(v.x, v.y);
}

__global__ __launch_bounds__(256)
void pack_pairs_cols(const float* __restrict__ B, u32* __restrict__ hi,
                     int N, int K)
{
    int i = blockIdx.x * 256 + threadIdx.x;
    int K2 = K >> 1;
    if (i >= K2 * N) return;
    int k2 = i / N, n = i - k2 * N;
    hi[i] = pack_f16(B[(size_t)(2 * k2) * N + n],
                     B[(size_t)(2 * k2 + 1) * N + n]);
}

__global__ __launch_bounds__(256)
void trig_table()
{
    int idx = blockIdx.x * 256 + threadIdx.x;
    if (idx >= TSEQ * 32) return;
    int t = idx >> 5, i = idx & 31;
    float freq = expf(-9.210340371976184f * (float)i * (1.0f / 32.0f));
    float ang = (float)t * freq;
    float s, c;
    sincosf(ang, &s, &c);
    g_trig[idx] = make_float2(s, c);
}

// ---------------------------------------------------------------------------
// mma_gemm8: single-pass fp16 GEMM, 3-stage cp.async, ldmatrix A-frags.
// epi=0: C=A@B+bias. epi=1: fused rope/pack -> q/k/v.
// ---------------------------------------------------------------------------
#define A_ST  (128 * 20)
#define B_ST  (16 * 136)
#define STG_U32 (A_ST + B_ST)              // 4736
#define G8_SMEM (128 * 129 * 4)            // 66048 B >= 3*STG_U32*4 = 56832

__global__ __launch_bounds__(256, 2)
void mma_gemm8(const u32* __restrict__ Agh, const u32* __restrict__ Bgh,
               float* __restrict__ C, const float* __restrict__ bias,
               int N, int K, int epi)
{
    extern __shared__ u32 sm8[];

    const int tid  = threadIdx.x;
    const int wid  = tid >> 5;
    const int lane = tid & 31;
    const int r8   = lane >> 2;
    const int c4   = lane & 3;
    const int grp  = lane >> 3;
    const int wtn  = lane & 7;
    const int wm   = (wid >> 2) * 64;
    const int wn   = (wid & 3) * 32;
    const int brow = blockIdx.y, bcol = blockIdx.x;
    const int K2   = K >> 1;

    const u32 smbase = (u32)__cvta_generic_to_shared(sm8);
    const u32 lmA = (u32)(((grp & 1) * 8 + wtn) * 20 + (grp >> 1) * 4);

    const int ar  = tid & 127;
    const int acb = (tid >> 7) * 8;
    const u32* Aph = Agh + (size_t)(brow * 128 + ar) * K2 + acb;
    const int bk  = tid >> 4;
    const int bnc = (tid & 15) * 8;
    const u32* Bph = Bgh + (size_t)bk * N + bcol * 128 + bnc;

    float acc[4][4][4];
    #pragma unroll
    for (int i = 0; i < 4; i++)
        #pragma unroll
        for (int j = 0; j < 4; j++)
            #pragma unroll
            for (int r = 0; r < 4; r++) acc[i][j][r] = 0.f;

    auto issue = [&](int k2base, int s) {
        u32* st = sm8 + s * STG_U32;
        u32* aH = st + ar * 20 + acb;
        cp16(aH,     Aph + k2base);
        cp16(aH + 4, Aph + k2base + 4);
        u32* bH = st + A_ST + bk * 136 + bnc;
        cp16(bH,     Bph + (size_t)k2base * N);
        cp16(bH + 4, Bph + (size_t)k2base * N + 4);
        asm volatile("cp.async.commit_group;");
    };

    issue(0, 0);
    issue(16, 1);

    const int nst = K2 >> 4;
    int s = 0;
    for (int ks = 0; ks < nst; ks++) {
        asm volatile("cp.async.wait_group 1;");
        __syncthreads();
        if (ks + 2 < nst) {
            int s2 = s + 2; if (s2 >= 3) s2 -= 3;
            issue((ks + 2) * 16, s2);
        } else {
            asm volatile("cp.async.commit_group;");
        }

        const u32 stoff = (u32)(s * STG_U32);
        const u32 aHb = smbase + (stoff + lmA + wm * 20) * 4;
        const u32* bH = sm8 + stoff + A_ST;

        #pragma unroll
        for (int kk = 0; kk < 2; kk++) {
            const int kc = kk * 8 + c4;
            u32 bh[4][2];
            #pragma unroll
            for (int nf = 0; nf < 4; nf++) {
                const int n = wn + nf * 8 + r8;
                bh[nf][0] = bH[kc * 136 + n];
                bh[nf][1] = bH[(kc + 4) * 136 + n];
            }
            #pragma unroll
            for (int mf = 0; mf < 4; mf++) {
                u32 ah[4];
                const u32 moff = (u32)(mf * 16 * 20 + kk * 8) * 4;
                ldsm_x4(ah, aHb + moff);
                #pragma unroll
                for (int nf = 0; nf < 4; nf++)
                    mma_f16(acc[mf][nf], ah, bh[nf]);
            }
        }
        if (++s >= 3) s -= 3;
    }

    if (!epi) {
        #pragma unroll
        for (int nf = 0; nf < 4; nf++) {
            const int cg = bcol * 128 + wn + nf * 8 + c4 * 2;
            float bx = bias ? bias[cg]     : 0.f;
            float by = bias ? bias[cg + 1] : 0.f;
            #pragma unroll
            for (int mf = 0; mf < 4; mf++) {
                const int rg = brow * 128 + wm + mf * 16 + r8;
                float2 v0 = make_float2(acc[mf][nf][0] + bx, acc[mf][nf][1] + by);
                float2 v1 = make_float2(acc[mf][nf][2] + bx, acc[mf][nf][3] + by);
                *(float2*)(C + (size_t)rg * N + cg)       = v0;
                *(float2*)(C + (size_t)(rg + 8) * N + cg) = v1;
            }
        }
    } else {
        // ---- fused epilogue: stage tile in smem, rope/pack/scatter ----
        asm volatile("cp.async.wait_group 0;" ::: "memory");
        __syncthreads();
        float* S = (float*)sm8;   // [128][129]
        #pragma unroll
        for (int nf = 0; nf < 4; nf++) {
            const int cg = wn + nf * 8 + c4 * 2;
            #pragma unroll
            for (int mf = 0; mf < 4; mf++) {
                const int rg = wm + mf * 16 + r8;
                S[rg * 129 + cg]           = acc[mf][nf][0];
                S[rg * 129 + cg + 1]       = acc[mf][nf][1];
                S[(rg + 8) * 129 + cg]     = acc[mf][nf][2];
                S[(rg + 8) * 129 + cg + 1] = acc[mf][nf][3];
            }
        }
        __syncthreads();

        const int which = bcol >> 3;     // 0=q 1=k 2=v
        const int b     = brow >> 4;
        if (which < 2) {
            for (int uu = 0; uu < 32; uu++) {
                const int u    = wid * 32 + uu;
                const int head = u >> 7;
                const int row  = u & 127;
                const int tt   = (brow & 15) * 128 + row;
                const int h    = (bcol & 7) * 2 + head;
                const int bh   = b * 16 + h;
                const float* Sr = S + row * 129 + head * 64;
                const int i = lane;
                const int j = (i < 16) ? 2 * i : 2 * i - 32;
                float4 tc = *(const float4*)(&g_trig[tt * 32 + j]); // s0,c0,s1,c1
                float a0 = Sr[j],      a1 = Sr[j + 1];
                float b0 = Sr[j + 32], b1 = Sr[j + 33];
                float e0, e1;
                if (i < 16) {
                    e0 = a0 * tc.y - b0 * tc.x;
                    e1 = a1 * tc.w - b1 * tc.z;
                } else {
                    e0 = a0 * tc.x + b0 * tc.y;
                    e1 = a1 * tc.z + b1 * tc.w;
                }
                size_t po = ((size_t)bh * TSEQ + tt) * 32 + i;
                if (which == 0) {
                    g_qh[po] = pack_f16(e0 * SCALE2, e1 * SCALE2);
                } else {
                    g_kh[po] = pack_f16(e0, e1);
                }
            }
        } else {
            const int dq  = tid >> 6;
            const int t2l = tid & 63;
            const int t2g = (brow & 15) * 64 + t2l;
            #pragma unroll 4
            for (int dd = dq; dd < 128; dd += 4) {
                const int h  = (bcol & 7) * 2 + (dd >> 6);
                const int bh = b * 16 + h;
                u32 pv = pack_f16(S[(2 * t2l) * 129 + dd],
                                  S[(2 * t2l + 1) * 129 + dd]);
                g_vth[((size_t)bh * HD + (dd & 63)) * (TSEQ / 2) + t2g] = pv;
            }
        }
    }
}

// ---------------------------------------------------------------------------
// Flash attention: fp16 single-pass S and PV, ldmatrix, cp.async double-
// buffered, exp2 softmax, 2 CTAs/SM. Epilogue writes packed o directly.
// ---------------------------------------------------------------------------
#define FKS  36
#define FTILE (64 * FKS)

__global__ __launch_bounds__(256, 2)
void flash_mma()
{
    __shared__ u32 Ksh[2 * FTILE];
    __shared__ u32 Vsh[2 * FTILE];

    const int bh   = blockIdx.y;
    const int qblk = gridDim.x - 1 - blockIdx.x;
    const int q0   = qblk * 128;

    const int tid  = threadIdx.x;
    const int w    = tid >> 5;
    const int lane = tid & 31;
    const int r8   = lane >> 2;
    const int c4   = lane & 3;
    const int grp  = lane >> 3;
    const int wtn  = lane & 7;

    const u32 Kbase = (u32)__cvta_generic_to_shared(Ksh);
    const u32 Vbase = (u32)__cvta_generic_to_shared(Vsh);
    const u32 lmF = (u32)(((grp >> 1) * 8 + wtn) * FKS + (grp & 1) * 4);

    u32 qh[4][4];
    {
        const u32* Qh = g_qh + ((size_t)bh * TSEQ + q0 + w * 16) * 32;
        #pragma unroll
        for (int g = 0; g < 4; g++) {
            qh[g][0] = Qh[(size_t)r8 * 32 + 8 * g + c4];
            qh[g][1] = Qh[(size_t)(r8 + 8) * 32 + 8 * g + c4];
            qh[g][2] = Qh[(size_t)r8 * 32 + 8 * g + c4 + 4];
            qh[g][3] = Qh[(size_t)(r8 + 8) * 32 + 8 * g + c4 + 4];
        }
    }

    float oacc[8][4];
    #pragma unroll
    for (int i = 0; i < 8; i++)
        #pragma unroll
        for (int j = 0; j < 4; j++) oacc[i][j] = 0.f;
    float m0 = -1e30f, m1 = -1e30f, l0 = 0.f, l1 = 0.f;

    const int row0 = q0 + w * 16 + r8;
    const int row1 = row0 + 8;

    const u32* Kgh = g_kh + (size_t)bh * TSEQ * 32;
    const u32* Vgh = g_vth + (size_t)bh * HD * (TSEQ / 2);

    const int lr = tid >> 2, lcb = (tid & 3) * 8;

    auto fissue = [&](int tile, int s) {
        const int k0 = tile * 64;
        const u32* kh = Kgh + (size_t)(k0 + lr) * 32 + lcb;
        const u32* vh = Vgh + (size_t)lr * (TSEQ / 2) + (k0 >> 1) + lcb;
        u32* dk = Ksh + s * FTILE + lr * FKS + lcb;
        u32* dv = Vsh + s * FTILE + lr * FKS + lcb;
        cp16(dk,     kh);
        cp16(dk + 4, kh + 4);
        cp16(dv,     vh);
        cp16(dv + 4, vh + 4);
        asm volatile("cp.async.commit_group;");
    };

    const int ntiles = 2 * qblk + 2;
    fissue(0, 0);

    for (int tile = 0; tile < ntiles; tile++) {
        asm volatile("cp.async.wait_group 0;");
        __syncthreads();
        if (tile + 1 < ntiles) fissue(tile + 1, (tile + 1) & 1);

        const u32 sboff = (u32)((tile & 1) * FTILE);
        const int k0 = tile * 64;

        const bool active = (k0 <= q0 + w * 16 + 15);
        if (active) {
            float sacc[8][4];
            #pragma unroll
            for (int i = 0; i < 8; i++)
                #pragma unroll
                for (int j = 0; j < 4; j++) sacc[i][j] = 0.f;

            const u32 kfb = Kbase + (sboff + lmF) * 4;
            #pragma unroll
            for (int g = 0; g < 4; g++) {
                #pragma unroll
                for (int nfp = 0; nfp < 4; nfp++) {
                    u32 kf[4];
                    ldsm_x4(kf, kfb + (u32)(nfp * 16 * FKS + 8 * g) * 4);
                    mma_f16(sacc[2 * nfp],     qh[g], kf);
                    mma_f16(sacc[2 * nfp + 1], qh[g], kf + 2);
                }
            }

            if (k0 + 63 > row0) {
                #pragma unroll
                for (int nf = 0; nf < 8; nf++) {
                    const int n0 = k0 + nf * 8 + 2 * c4;
                    if (n0 > row0)     sacc[nf][0] = -1e30f;
                    if (n0 + 1 > row0) sacc[nf][1] = -1e30f;
                    if (n0 > row1)     sacc[nf][2] = -1e30f;
                    if (n0 + 1 > row1) sacc[nf][3] = -1e30f;
                }
            }

            float rm0 = -1e30f, rm1 = -1e30f;
            #pragma unroll
            for (int nf = 0; nf < 8; nf++) {
                rm0 = fmaxf(rm0, fmaxf(sacc[nf][0], sacc[nf][1]));
                rm1 = fmaxf(rm1, fmaxf(sacc[nf][2], sacc[nf][3]));
            }
            rm0 = fmaxf(rm0, __shfl_xor_sync(0xffffffffu, rm0, 1));
            rm0 = fmaxf(rm0, __shfl_xor_sync(0xffffffffu, rm0, 2));
            rm1 = fmaxf(rm1, __shfl_xor_sync(0xffffffffu, rm1, 1));
            rm1 = fmaxf(rm1, __shfl_xor_sync(0xffffffffu, rm1, 2));

            const float mn0 = fmaxf(m0, rm0);
            const float mn1 = fmaxf(m1, rm1);
            const float rs0 = exp2_fast(m0 - mn0);
            const float rs1 = exp2_fast(m1 - mn1);
            m0 = mn0; m1 = mn1;

            float sum0 = 0.f, sum1 = 0.f;
            #pragma unroll
            for (int nf = 0; nf < 8; nf++) {
                sacc[nf][0] = exp2_fast(sacc[nf][0] - mn0);
                sacc[nf][1] = exp2_fast(sacc[nf][1] - mn0);
                sacc[nf][2] = exp2_fast(sacc[nf][2] - mn1);
                sacc[nf][3] = exp2_fast(sacc[nf][3] - mn1);
                sum0 += sacc[nf][0] + sacc[nf][1];
                sum1 += sacc[nf][2] + sacc[nf][3];
            }
            sum0 += __shfl_xor_sync(0xffffffffu, sum0, 1);
            sum0 += __shfl_xor_sync(0xffffffffu, sum0, 2);
            sum1 += __shfl_xor_sync(0xffffffffu, sum1, 1);
            sum1 += __shfl_xor_sync(0xffffffffu, sum1, 2);
            l0 = l0 * rs0 + sum0;
            l1 = l1 * rs1 + sum1;

            #pragma unroll
            for (int nf = 0; nf < 8; nf++) {
                oacc[nf][0] *= rs0;
                oacc[nf][1] *= rs0;
                oacc[nf][2] *= rs1;
                oacc[nf][3] *= rs1;
            }

            const u32 vfb = Vbase + (sboff + lmF) * 4;
            #pragma unroll
            for (int g = 0; g < 4; g++) {
                u32 ph[4];
                ph[0] = pack_f16(sacc[2 * g][0],     sacc[2 * g][1]);
                ph[1] = pack_f16(sacc[2 * g][2],     sacc[2 * g][3]);
                ph[2] = pack_f16(sacc[2 * g + 1][0], sacc[2 * g + 1][1]);
                ph[3] = pack_f16(sacc[2 * g + 1][2], sacc[2 * g + 1][3]);
                #pragma unroll
                for (int nfp = 0; nfp < 4; nfp++) {
                    u32 vf[4];
                    ldsm_x4(vf, vfb + (u32)(nfp * 16 * FKS + 8 * g) * 4);
                    mma_f16(oacc[2 * nfp],     ph, vf);
                    mma_f16(oacc[2 * nfp + 1], ph, vf + 2);
                }
            }
        }
    }

    // epilogue: normalize and write packed fp16 o directly (proj A-operand)
    const float inv0 = 1.0f / l0;
    const float inv1 = 1.0f / l1;
    const int b = bh >> 4, h = bh & 15;
    #pragma unroll
    for (int nf = 0; nf < 8; nf++) {
        const size_t i0 = ((size_t)(b * TSEQ) + row0) * 512 + h * 32 + nf * 4 + c4;
        const size_t i1 = ((size_t)(b * TSEQ) + row1) * 512 + h * 32 + nf * 4 + c4;
        g_oh2[i0] = pack_f16(oacc[nf][0] * inv0, oacc[nf][1] * inv0);
        g_oh2[i1] = pack_f16(oacc[nf][2] * inv1, oacc[nf][3] * inv1);
    }
}

// ---------------------------------------------------------------------------
extern "C" void kernel_launch(void* const* d_in, const int* in_sizes, int n_in,
                              void* d_out, int out_size)
{
    const float* x      = (const float*)d_in[0];
    const float* w_qkv  = (const float*)d_in[1];
    const float* w_proj = (const float*)d_in[2];
    const float* b_proj = (const float*)d_in[3];
    float* out = (float*)d_out;

    u32 *xh, *oh, *wqh, *wph;
    cudaGetSymbolAddress((void**)&xh,  g_xh);
    cudaGetSymbolAddress((void**)&oh,  g_oh2);
    cudaGetSymbolAddress((void**)&wqh, g_wqh);
    cudaGetSymbolAddress((void**)&wph, g_wph);

    cudaFuncSetAttribute(mma_gemm8,
                         cudaFuncAttributeMaxDynamicSharedMemorySize, G8_SMEM);

    // 0) trig table + operand prepasses
    trig_table<<<(TSEQ * 32 + 255) / 256, 256>>>();
    const int xpairs = TOKENS * DIM / 2;
    pack_pairs_rows<<<(xpairs + 255) / 256, 256>>>(x, xh, xpairs);
    pack_pairs_cols<<<((DIM / 2) * QKV_N + 255) / 256, 256>>>(w_qkv, wqh, QKV_N, DIM);
    pack_pairs_cols<<<((DIM / 2) * DIM + 255) / 256, 256>>>(w_proj, wph, DIM, DIM);

    // 1) qkv = x @ w_qkv -> fused rope/pack -> g_qh/g_kh/g_vth
    mma_gemm8<<<dim3(QKV_N / 128, TOKENS / 128), 256, G8_SMEM>>>(
        xh, wqh, nullptr, nullptr, QKV_N, DIM, 1);

    // 2) flash attention (writes packed o directly)
    flash_mma<<<dim3(TSEQ / 128, BHEADS), 256>>>();

    // 3) out = o @ w_proj + b_proj
    mma_gemm8<<<dim3(DIM / 128, TOKENS / 128), 256, G8_SMEM>>>(
        oh, wph, out, b_proj, DIM, DIM, 0);
}